// round 14
// baseline (speedup 1.0000x reference)
#include <cuda_runtime.h>
#include <cuda_fp16.h>
#include <math.h>
#include <stdint.h>

// ===================== problem constants =====================
#define NB   16
#define NC   256
#define NHW  1024
#define NTOK (NB * NHW)        // 16384
#define NK   8192
#define NQ   (NB * NC * NHW)   // 4194304

#define DELTA 0.75f
#define CAND_CAP 16
#define CK_STRIDE 64

// ===================== device scratch =====================
__device__ __align__(16) uint32_t g_zfrag[(NTOK / 128) * 16384];  // 8MB, frag-order A (fp16 pairs)
__device__ __align__(16) __half g_ehf[NK * NC];                   // 4MB, fp16(-2e)
__device__ __align__(16) float g_zt[NTOK * NC];                   // 16MB, z transposed [n][c]
__device__ float  g_cbnorm[NK];
__device__ __align__(16) int g_idx[NTOK];
__device__ int    g_nc[NTOK];
__device__ int    g_ck[NTOK * CK_STRIDE];
__device__ int    g_counts[NK];
__device__ double g_loss;

__device__ __forceinline__ uint32_t smem_u32(const void* p) {
    uint32_t a;
    asm("{ .reg .u64 t; cvta.to.shared.u64 t, %1; cvt.u32.u64 %0, t; }" : "=r"(a) : "l"(p));
    return a;
}

// ===================== prep z: 64x64 float4 tiles, fp16 frags ======================
__global__ void vq_prep_z_kernel(const float* __restrict__ z) {
    __shared__ float t[64][65];
    __shared__ uint32_t fr[2048];
    const int b   = blockIdx.z;
    const int c0  = blockIdx.y * 64;
    const int hw0 = blockIdx.x * 64;
    const int tid = threadIdx.x;
    const int jj  = tid & 15;
    const int ii  = tid >> 4;

    const float* zb = z + ((size_t)b * NC + c0) * NHW + hw0;
#pragma unroll
    for (int i = 0; i < 4; i++) {
        int cr = i * 16 + ii;
        float4 v = *(const float4*)(zb + (size_t)cr * NHW + 4 * jj);
        t[cr][4 * jj]     = v.x;
        t[cr][4 * jj + 1] = v.y;
        t[cr][4 * jj + 2] = v.z;
        t[cr][4 * jj + 3] = v.w;
    }
    __syncthreads();

#pragma unroll
    for (int i = 0; i < 4; i++) {
        int hwi = i * 16 + ii;
        int n = b * NHW + hw0 + hwi;
        float4 v;
        v.x = t[4 * jj][hwi];
        v.y = t[4 * jj + 1][hwi];
        v.z = t[4 * jj + 2][hwi];
        v.w = t[4 * jj + 3][hwi];
        *(float4*)(g_zt + (size_t)n * NC + c0 + 4 * jj) = v;
    }

#pragma unroll
    for (int e = 0; e < 8; e++) {
        int fid = tid * 8 + e;
        int r   = fid & 3;
        int l   = (fid >> 2) & 31;
        int mtl = (fid >> 7) & 3;
        int ks  = fid >> 9;
        int gg  = l >> 2, tg = l & 3;
        int rl  = r & 1,  rh = r >> 1;
        int cl  = ks * 16 + tg * 2 + rh * 8;
        int hwi = mtl * 16 + rl * 8 + gg;
        float v0 = t[cl][hwi];
        float v1 = t[cl + 1][hwi];
        uint32_t lo = (uint32_t)__half_as_ushort(__float2half_rn(v0));
        uint32_t hi = (uint32_t)__half_as_ushort(__float2half_rn(v1));
        fr[fid] = lo | (hi << 16);
    }
    __syncthreads();

    {
        int n0  = b * NHW + hw0;
        int blk = n0 >> 7;
        int mt0 = (n0 & 127) >> 4;
        int ks0 = c0 >> 4;
        uint4* dst4 = (uint4*)g_zfrag;
        const uint4* fr4 = (const uint4*)fr;
#pragma unroll
        for (int e = 0; e < 2; e++) {
            int q   = tid + e * 256;
            int off = q & 31;
            int mtl = (q >> 5) & 3;
            int ks  = q >> 7;
            dst4[(size_t)((blk * 16 + ks0 + ks) * 8 + (mt0 + mtl)) * 32 + off] = fr4[q];
        }
    }
}

// ===================== fused prep: cbnorm + fp16(-2e) + init =====================
__global__ void vq_prep_cb_kernel(const float* __restrict__ cb) {
    int row  = blockIdx.x * 8 + (threadIdx.x >> 5);
    int lane = threadIdx.x & 31;
    const float* rp = cb + (size_t)row * NC;
    float v[8];
    float s = 0.f;
#pragma unroll
    for (int i = 0; i < 8; i++) {
        v[i] = rp[lane + i * 32];
        s += v[i] * v[i];
    }
#pragma unroll
    for (int off = 16; off; off >>= 1) s += __shfl_down_sync(0xffffffffu, s, off);
    if (lane == 0) g_cbnorm[row] = s;
#pragma unroll
    for (int i = 0; i < 8; i++)
        g_ehf[(size_t)row * NC + lane + i * 32] = __float2half_rn(-2.0f * v[i]);
    int gid = blockIdx.x * 256 + threadIdx.x;
    if (gid < NK) g_counts[gid] = 0;
    if (gid == 0) g_loss = 0.0;
}

// ===================== main kernel: fp16-accum HMMA + candidate filter ==========
#define SM_A      0
#define SM_B      65536
#define SM_BSTG   18432
#define BROW_STRIDE 144
#define SM_CBN    102400
#define SM_SNC    135168
#define SM_SCAND  137216
#define SM_SCANDD 169984
#define SM_SMINV  202752
#define SM_TOTAL  204800

__global__ void __launch_bounds__(512, 1) vq_argmin_mma_kernel() {
    extern __shared__ char smem[];
    uint32_t sb = smem_u32(smem);
    const int tid  = threadIdx.x;
    const int wid  = tid >> 5;
    const int lane = tid & 31;
    const int wm   = wid >> 2;       // 0..3
    const int wn   = wid & 3;        // 0..3
    const int g    = lane >> 2;      // 0..7
    const int tg   = lane & 3;       // 0..3
    const int blk  = blockIdx.x;
    const int n_base = blk * 128;

    uint4*  Asm    = (uint4*)(smem + SM_A);
    float*  cbn    = (float*)(smem + SM_CBN);
    int*    snc    = (int*)(smem + SM_SNC);
    int*    scand  = (int*)(smem + SM_SCAND);
    float*  scandd = (float*)(smem + SM_SCANDD);
    float*  sminv  = (float*)(smem + SM_SMINV);

    // ---- stage A frags + cbnorm, zero counters ----
    {
        const uint4* src = (const uint4*)(g_zfrag + (size_t)blk * 16384);
#pragma unroll
        for (int i = 0; i < 8; i++) Asm[tid + i * 512] = src[tid + i * 512];
        const float4* cs = (const float4*)g_cbnorm;
        float4* cd = (float4*)cbn;
#pragma unroll
        for (int i = 0; i < 4; i++) cd[tid + i * 512] = cs[tid + i * 512];
        snc[tid] = 0;
    }
    __syncthreads();

    // ---- cp.async B loader ----
    const int brow = tid >> 2;        // 0..127
    const int bq   = tid & 3;         // 32B quarter
    {
        const char* src = (const char*)(g_ehf) + (size_t)brow * 512 + bq * 32;
        uint32_t dst = sb + SM_B + brow * BROW_STRIDE + bq * 32;
        asm volatile("cp.async.cg.shared.global [%0], [%1], 16;" :: "r"(dst), "l"(src));
        asm volatile("cp.async.cg.shared.global [%0], [%1], 16;" :: "r"(dst + 16), "l"(src + 16));
        asm volatile("cp.async.commit_group;" ::: "memory");
    }

    uint32_t acc[2][4][2];           // half2 accumulators
    float minv[4];
#pragma unroll
    for (int i = 0; i < 4; i++) minv[i] = 3.4e38f;

    const int rowsel = lane >> 4;
    const int kbsel  = ((lane >> 3) & 1) * 16;
    const uint32_t bA1 = (uint32_t)(((wn * 4 + rowsel) * 8 + (lane & 7)) * BROW_STRIDE + kbsel);
    const uint32_t bA2 = (uint32_t)(((wn * 4 + 2 + rowsel) * 8 + (lane & 7)) * BROW_STRIDE + kbsel);

    for (int T = 0; T < 256; T++) {
        const int tile = T >> 2;
        const int q2   = T & 3;

        asm volatile("cp.async.wait_group 0;" ::: "memory");
        __syncthreads();

        if (T + 1 < 256) {
            const int Tn = T + 1;
            const char* src = (const char*)(g_ehf) +
                (size_t)((Tn >> 2) * 128 + brow) * 512 + (Tn & 3) * 128 + bq * 32;
            uint32_t dst = sb + SM_B + ((Tn & 1) * SM_BSTG) + brow * BROW_STRIDE + bq * 32;
            asm volatile("cp.async.cg.shared.global [%0], [%1], 16;" :: "r"(dst), "l"(src));
            asm volatile("cp.async.cg.shared.global [%0], [%1], 16;" :: "r"(dst + 16), "l"(src + 16));
            asm volatile("cp.async.commit_group;" ::: "memory");
        }

        if (q2 == 0) {
#pragma unroll
            for (int m = 0; m < 2; m++)
#pragma unroll
                for (int j = 0; j < 4; j++) {
                    acc[m][j][0] = 0u;
                    acc[m][j][1] = 0u;
                }
        }

        const uint32_t bbase = sb + SM_B + (T & 1) * SM_BSTG;
#pragma unroll
        for (int s2 = 0; s2 < 4; s2++) {
            const int ks = q2 * 4 + s2;
            uint32_t a[2][4];
#pragma unroll
            for (int m2 = 0; m2 < 2; m2++) {
                uint4 v = Asm[(ks * 8 + (wm * 2 + m2)) * 32 + lane];
                a[m2][0] = v.x; a[m2][1] = v.y; a[m2][2] = v.z; a[m2][3] = v.w;
            }
            uint32_t b[4][2];
            asm volatile("ldmatrix.sync.aligned.m8n8.x4.shared.b16 {%0,%1,%2,%3}, [%4];"
                : "=r"(b[0][0]), "=r"(b[0][1]), "=r"(b[1][0]), "=r"(b[1][1])
                : "r"(bbase + bA1 + s2 * 32));
            asm volatile("ldmatrix.sync.aligned.m8n8.x4.shared.b16 {%0,%1,%2,%3}, [%4];"
                : "=r"(b[2][0]), "=r"(b[2][1]), "=r"(b[3][0]), "=r"(b[3][1])
                : "r"(bbase + bA2 + s2 * 32));
#pragma unroll
            for (int m2 = 0; m2 < 2; m2++)
#pragma unroll
                for (int j = 0; j < 4; j++) {
                    asm volatile(
                        "mma.sync.aligned.m16n8k16.row.col.f16.f16.f16.f16 "
                        "{%0,%1}, {%2,%3,%4,%5}, {%6,%7}, {%0,%1};"
                        : "+r"(acc[m2][j][0]), "+r"(acc[m2][j][1])
                        : "r"(a[m2][0]), "r"(a[m2][1]), "r"(a[m2][2]), "r"(a[m2][3]),
                          "r"(b[j][0]), "r"(b[j][1]));
                }
        }

        if (q2 == 3) {
            const int nb = tile * 128 + wn * 32;
            float2 cb2[4];
#pragma unroll
            for (int j = 0; j < 4; j++)
                cb2[j] = *(const float2*)(cbn + nb + j * 8 + 2 * tg);
#pragma unroll
            for (int mh = 0; mh < 4; mh++) {
                const int m = mh >> 1, h = mh & 1;
                float d0[8];
#pragma unroll
                for (int j = 0; j < 4; j++) {
                    float2 av = __half22float2(*(const __half2*)&acc[m][j][h]);
                    d0[2 * j]     = av.x + cb2[j].x;
                    d0[2 * j + 1] = av.y + cb2[j].y;
                }
                float lm = d0[0];
#pragma unroll
                for (int i = 1; i < 8; i++) lm = fminf(lm, d0[i]);
                lm = fminf(lm, __shfl_xor_sync(0xffffffffu, lm, 1));
                lm = fminf(lm, __shfl_xor_sync(0xffffffffu, lm, 2));
                if (lm < minv[mh] + DELTA) {
                    const float thr2 = fminf(minv[mh], lm) + DELTA;
                    const int tl = m * 16 + h * 8 + g;
#pragma unroll
                    for (int j = 0; j < 4; j++)
#pragma unroll
                        for (int p = 0; p < 2; p++) {
                            float d = d0[2 * j + p];
                            if (d < thr2) {
                                int slot = atomicAdd(&snc[wid * 32 + tl], 1);
                                if (slot < CAND_CAP) {
                                    scand[(wid * 32 + tl) * CAND_CAP + slot] =
                                        nb + j * 8 + 2 * tg + p;
                                    scandd[(wid * 32 + tl) * CAND_CAP + slot] = d;
                                }
                            }
                        }
                    minv[mh] = fminf(minv[mh], lm);
                }
            }
        }
    }

    if (tg == 0) {
#pragma unroll
        for (int mh = 0; mh < 4; mh++) {
            const int tl = (mh >> 1) * 16 + (mh & 1) * 8 + g;
            sminv[wid * 32 + tl] = minv[mh];
        }
    }
    __syncthreads();

    // -------- merge + filter --------
    if (tid < 128) {
        const int wmg = tid >> 5, tl = tid & 31;
        const int tok = n_base + tid;
        float gmin = 3.4e38f;
#pragma unroll
        for (int j = 0; j < 4; j++)
            gmin = fminf(gmin, sminv[(wmg * 4 + j) * 32 + tl]);
        const float thr = gmin + DELTA;
        int total = 0;
        bool ovf = false;
        for (int j = 0; j < 4; j++) {
            const int w = wmg * 4 + j;
            int cnum = snc[w * 32 + tl];
            if (cnum > CAND_CAP) { ovf = true; cnum = CAND_CAP; }
            for (int s = 0; s < cnum; s++) {
                if (scandd[(w * 32 + tl) * CAND_CAP + s] <= thr) {
                    g_ck[tok * CK_STRIDE + total] = scand[(w * 32 + tl) * CAND_CAP + s];
                    total++;
                }
            }
        }
        g_nc[tok] = ovf ? 255 : total;
    }
}

// ===================== exact rescoring (fast path nc==1) =====================
__device__ __forceinline__ float vq_exact_dist(const float* __restrict__ cb,
                                               const float zr[8], int k, int lane) {
    const float* cr = cb + (size_t)k * NC + lane;
    float s = 0.f;
#pragma unroll
    for (int u = 0; u < 8; u++) s += zr[u] * cr[u * 32];
#pragma unroll
    for (int off = 16; off; off >>= 1) s += __shfl_xor_sync(0xffffffffu, s, off);
    return g_cbnorm[k] - 2.0f * s;
}

__global__ void vq_rescore_kernel(const float* __restrict__ cb) {
    int n = (blockIdx.x * blockDim.x + threadIdx.x) >> 5;
    int lane = threadIdx.x & 31;
    if (n >= NTOK) return;
    int nc = g_nc[n];

    if (nc == 1) {
        if (lane == 0) g_idx[n] = g_ck[n * CK_STRIDE];
        return;
    }

    const float* zp = g_zt + (size_t)n * NC;
    float zr[8];
#pragma unroll
    for (int u = 0; u < 8; u++) zr[u] = zp[lane + u * 32];

    float bd = 3.4e38f;
    int bk = 0x7fffffff;
    if (nc < 255) {
        for (int i = 0; i < nc; i++) {
            int k = g_ck[n * CK_STRIDE + i];
            float d = vq_exact_dist(cb, zr, k, lane);
            if (d < bd || (d == bd && k < bk)) { bd = d; bk = k; }
        }
    } else {
        for (int k = 0; k < NK; k++) {
            float d = vq_exact_dist(cb, zr, k, lane);
            if (d < bd || (d == bd && k < bk)) { bd = d; bk = k; }
        }
    }
    if (lane == 0) g_idx[n] = bk;
}

// ===================== writeback =====================
__global__ void vq_writeback_kernel(const float* __restrict__ z, const float* __restrict__ cb,
                                    float* __restrict__ out) {
    const int tid = threadIdx.x;
    const int gid = blockIdx.x * 256 + tid;
    const int hw  = gid & 1023;
    const int cq  = (gid >> 10) & 63;
    const int b   = gid >> 16;
    const int n   = (b << 10) | hw;
    const int c   = cq * 4;

    const int k = g_idx[n];
    float4 q = *(const float4*)(cb + (size_t)k * NC + c);

    const size_t zbase = ((size_t)b * NC + c) * NHW + hw;
    float zv0 = z[zbase];
    float zv1 = z[zbase + NHW];
    float zv2 = z[zbase + 2 * NHW];
    float zv3 = z[zbase + 3 * NHW];

    out[zbase]           = zv0 + (q.x - zv0);
    out[zbase + NHW]     = zv1 + (q.y - zv1);
    out[zbase + 2 * NHW] = zv2 + (q.z - zv2);
    out[zbase + 3 * NHW] = zv3 + (q.w - zv3);

    if (cq == 0) {
        atomicAdd(&g_counts[k], 1);
        out[NQ + n] = (float)k;
    }

    float dx = zv0 - q.x, dy = zv1 - q.y, dz = zv2 - q.z, dw = zv3 - q.w;
    double s = (double)dx * dx + (double)dy * dy + (double)dz * dz + (double)dw * dw;
#pragma unroll
    for (int off = 16; off; off >>= 1) s += __shfl_down_sync(0xffffffffu, s, off);
    __shared__ double ws[8];
    if ((tid & 31) == 0) ws[tid >> 5] = s;
    __syncthreads();
    if (tid == 0) {
        double t = 0.0;
#pragma unroll
        for (int i = 0; i < 8; i++) t += ws[i];
        atomicAdd(&g_loss, t);
    }
}

// ===================== finalize =====================
__global__ void vq_finalize_kernel(float* __restrict__ out) {
    const int tid = threadIdx.x;
    double s = 0.0;
    for (int k = tid; k < NK; k += 256) {
        int c = g_counts[k];
        if (c > 0) {
            double p = (double)c / (double)NTOK;
            s += p * log(p);
        }
    }
#pragma unroll
    for (int off = 16; off; off >>= 1) s += __shfl_down_sync(0xffffffffu, s, off);
    __shared__ double ws[8];
    if ((tid & 31) == 0) ws[tid >> 5] = s;
    __syncthreads();
    if (tid == 0) {
        double t = 0.0;
#pragma unroll
        for (int i = 0; i < 8; i++) t += ws[i];
        float perp = (float)exp(-t);
        float loss = (float)(g_loss / (double)NQ);
        out[NQ + NTOK + 0] = perp;
        out[NQ + NTOK + 1] = loss;
        out[NQ + NTOK + 2] = loss;
    }
}

// ===================== launch =====================
extern "C" void kernel_launch(void* const* d_in, const int* in_sizes, int n_in,
                              void* d_out, int out_size) {
    const float* z  = (const float*)d_in[0];
    const float* cb = (const float*)d_in[1];
    float* out = (float*)d_out;

    static bool attr_set = false;
    if (!attr_set) {
        cudaFuncSetAttribute(vq_argmin_mma_kernel,
                             cudaFuncAttributeMaxDynamicSharedMemorySize, SM_TOTAL);
        attr_set = true;
    }

    vq_prep_z_kernel<<<dim3(16, 4, 16), 256>>>(z);
    vq_prep_cb_kernel<<<NK / 8, 256>>>(cb);
    vq_argmin_mma_kernel<<<NTOK / 128, 512, SM_TOTAL>>>();
    vq_rescore_kernel<<<NTOK / 8, 256>>>(cb);
    vq_writeback_kernel<<<NQ / 1024, 256>>>(z, cb, out);
    vq_finalize_kernel<<<1, 256>>>(out);
}

// round 15
// speedup vs baseline: 1.0319x; 1.0319x over previous
#include <cuda_runtime.h>
#include <cuda_bf16.h>
#include <math.h>
#include <stdint.h>

// ===================== problem constants =====================
#define NB   16
#define NC   256
#define NHW  1024
#define NTOK (NB * NHW)        // 16384
#define NK   8192
#define NQ   (NB * NC * NHW)   // 4194304

#define DELTA 0.75f
#define CAND_CAP 16
#define CK_STRIDE 64

// ===================== device scratch =====================
__device__ __align__(16) uint32_t g_zfrag[(NTOK / 128) * 16384];  // 8MB, frag-order A
__device__ __align__(16) __nv_bfloat16 g_ebf[NK * NC];            // 4MB, bf16(-2e)
__device__ __align__(16) float g_zt[NTOK * NC];                   // 16MB, z transposed [n][c]
__device__ float  g_cbnorm[NK];
__device__ __align__(16) int g_idx[NTOK];
__device__ int    g_nc[NTOK];
__device__ int    g_ck[NTOK * CK_STRIDE];
__device__ int    g_counts[NK];
__device__ double g_loss;

__device__ __forceinline__ uint32_t smem_u32(const void* p) {
    uint32_t a;
    asm("{ .reg .u64 t; cvta.to.shared.u64 t, %1; cvt.u32.u64 %0, t; }" : "=r"(a) : "l"(p));
    return a;
}

// ===================== fused prep: z tiles (bid<1024) + codebook (bid>=1024) ======
__global__ void vq_prep_kernel(const float* __restrict__ z, const float* __restrict__ cb) {
    __shared__ float t[64][65];
    __shared__ uint32_t fr[2048];
    const int tid = threadIdx.x;

    if (blockIdx.x < 1024) {
        // ---------------- prep_z: 64 channels x 64 tokens ----------------
        const int bid = blockIdx.x;
        const int b   = bid >> 6;
        const int c0  = ((bid >> 4) & 3) * 64;
        const int hw0 = (bid & 15) * 64;
        const int jj  = tid & 15;
        const int ii  = tid >> 4;

        const float* zb = z + ((size_t)b * NC + c0) * NHW + hw0;
#pragma unroll
        for (int i = 0; i < 4; i++) {
            int cr = i * 16 + ii;
            float4 v = *(const float4*)(zb + (size_t)cr * NHW + 4 * jj);
            t[cr][4 * jj]     = v.x;
            t[cr][4 * jj + 1] = v.y;
            t[cr][4 * jj + 2] = v.z;
            t[cr][4 * jj + 3] = v.w;
        }
        __syncthreads();

#pragma unroll
        for (int i = 0; i < 4; i++) {
            int hwi = i * 16 + ii;
            int n = b * NHW + hw0 + hwi;
            float4 v;
            v.x = t[4 * jj][hwi];
            v.y = t[4 * jj + 1][hwi];
            v.z = t[4 * jj + 2][hwi];
            v.w = t[4 * jj + 3][hwi];
            *(float4*)(g_zt + (size_t)n * NC + c0 + 4 * jj) = v;
        }

#pragma unroll
        for (int e = 0; e < 8; e++) {
            int fid = tid * 8 + e;
            int r   = fid & 3;
            int l   = (fid >> 2) & 31;
            int mtl = (fid >> 7) & 3;
            int ks  = fid >> 9;
            int gg  = l >> 2, tg = l & 3;
            int rl  = r & 1,  rh = r >> 1;
            int cl  = ks * 16 + tg * 2 + rh * 8;
            int hwi = mtl * 16 + rl * 8 + gg;
            float v0 = t[cl][hwi];
            float v1 = t[cl + 1][hwi];
            uint32_t lo = (uint32_t)__bfloat16_as_ushort(__float2bfloat16(v0));
            uint32_t hi = (uint32_t)__bfloat16_as_ushort(__float2bfloat16(v1));
            fr[fid] = lo | (hi << 16);
        }
        __syncthreads();

        {
            int n0  = b * NHW + hw0;
            int blk = n0 >> 7;
            int mt0 = (n0 & 127) >> 4;
            int ks0 = c0 >> 4;
            uint4* dst4 = (uint4*)g_zfrag;
            const uint4* fr4 = (const uint4*)fr;
#pragma unroll
            for (int e = 0; e < 2; e++) {
                int q   = tid + e * 256;
                int off = q & 31;
                int mtl = (q >> 5) & 3;
                int ks  = q >> 7;
                dst4[(size_t)((blk * 16 + ks0 + ks) * 8 + (mt0 + mtl)) * 32 + off] = fr4[q];
            }
        }
    } else {
        // ---------------- prep_cb: cbnorm + bf16(-2e) + init ----------------
        const int cbid = blockIdx.x - 1024;
        int row  = cbid * 8 + (tid >> 5);
        int lane = tid & 31;
        const float* rp = cb + (size_t)row * NC;
        float v[8];
        float s = 0.f;
#pragma unroll
        for (int i = 0; i < 8; i++) {
            v[i] = rp[lane + i * 32];
            s += v[i] * v[i];
        }
#pragma unroll
        for (int off = 16; off; off >>= 1) s += __shfl_down_sync(0xffffffffu, s, off);
        if (lane == 0) g_cbnorm[row] = s;
#pragma unroll
        for (int i = 0; i < 8; i++)
            g_ebf[(size_t)row * NC + lane + i * 32] = __float2bfloat16(-2.0f * v[i]);
        int gid = cbid * 256 + tid;
        if (gid < NK) g_counts[gid] = 0;
        if (gid == 0) g_loss = 0.0;
    }
}

// ===================== main kernel: R7 body + candidate-distance filter ==========
#define SM_A      0
#define SM_B      65536
#define SM_BSTG   18432
#define BROW_STRIDE 144
#define SM_CBN    102400
#define SM_SNC    135168
#define SM_SCAND  137216
#define SM_SCANDD 169984
#define SM_SMINV  202752
#define SM_TOTAL  204800

__global__ void __launch_bounds__(512, 1) vq_argmin_mma_kernel() {
    extern __shared__ char smem[];
    uint32_t sb = smem_u32(smem);
    const int tid  = threadIdx.x;
    const int wid  = tid >> 5;
    const int lane = tid & 31;
    const int wm   = wid >> 2;       // 0..3
    const int wn   = wid & 3;        // 0..3
    const int g    = lane >> 2;      // 0..7
    const int tg   = lane & 3;       // 0..3
    const int blk  = blockIdx.x;
    const int n_base = blk * 128;

    uint4*  Asm    = (uint4*)(smem + SM_A);
    float*  cbn    = (float*)(smem + SM_CBN);
    int*    snc    = (int*)(smem + SM_SNC);
    int*    scand  = (int*)(smem + SM_SCAND);
    float*  scandd = (float*)(smem + SM_SCANDD);
    float*  sminv  = (float*)(smem + SM_SMINV);

    // ---- stage A frags + cbnorm, zero counters ----
    {
        const uint4* src = (const uint4*)(g_zfrag + (size_t)blk * 16384);
#pragma unroll
        for (int i = 0; i < 8; i++) Asm[tid + i * 512] = src[tid + i * 512];
        const float4* cs = (const float4*)g_cbnorm;
        float4* cd = (float4*)cbn;
#pragma unroll
        for (int i = 0; i < 4; i++) cd[tid + i * 512] = cs[tid + i * 512];
        snc[tid] = 0;
    }
    __syncthreads();

    // ---- cp.async B loader ----
    const int brow = tid >> 2;        // 0..127
    const int bq   = tid & 3;         // 32B quarter
    {
        const char* src = (const char*)(g_ebf) + (size_t)brow * 512 + bq * 32;
        uint32_t dst = sb + SM_B + brow * BROW_STRIDE + bq * 32;
        asm volatile("cp.async.cg.shared.global [%0], [%1], 16;" :: "r"(dst), "l"(src));
        asm volatile("cp.async.cg.shared.global [%0], [%1], 16;" :: "r"(dst + 16), "l"(src + 16));
        asm volatile("cp.async.commit_group;" ::: "memory");
    }

    float acc[2][4][4];
    float minv[4];
#pragma unroll
    for (int i = 0; i < 4; i++) minv[i] = 3.4e38f;

    const int rowsel = lane >> 4;
    const int kbsel  = ((lane >> 3) & 1) * 16;
    const uint32_t bA1 = (uint32_t)(((wn * 4 + rowsel) * 8 + (lane & 7)) * BROW_STRIDE + kbsel);
    const uint32_t bA2 = (uint32_t)(((wn * 4 + 2 + rowsel) * 8 + (lane & 7)) * BROW_STRIDE + kbsel);

    for (int T = 0; T < 256; T++) {
        const int tile = T >> 2;
        const int q2   = T & 3;

        asm volatile("cp.async.wait_group 0;" ::: "memory");
        __syncthreads();

        if (T + 1 < 256) {
            const int Tn = T + 1;
            const char* src = (const char*)(g_ebf) +
                (size_t)((Tn >> 2) * 128 + brow) * 512 + (Tn & 3) * 128 + bq * 32;
            uint32_t dst = sb + SM_B + ((Tn & 1) * SM_BSTG) + brow * BROW_STRIDE + bq * 32;
            asm volatile("cp.async.cg.shared.global [%0], [%1], 16;" :: "r"(dst), "l"(src));
            asm volatile("cp.async.cg.shared.global [%0], [%1], 16;" :: "r"(dst + 16), "l"(src + 16));
            asm volatile("cp.async.commit_group;" ::: "memory");
        }

        if (q2 == 0) {
#pragma unroll
            for (int m = 0; m < 2; m++)
#pragma unroll
                for (int j = 0; j < 4; j++)
#pragma unroll
                    for (int r = 0; r < 4; r++) acc[m][j][r] = 0.f;
        }

        const uint32_t bbase = sb + SM_B + (T & 1) * SM_BSTG;
#pragma unroll
        for (int s2 = 0; s2 < 4; s2++) {
            const int ks = q2 * 4 + s2;
            uint32_t a[2][4];
#pragma unroll
            for (int m2 = 0; m2 < 2; m2++) {
                uint4 v = Asm[(ks * 8 + (wm * 2 + m2)) * 32 + lane];
                a[m2][0] = v.x; a[m2][1] = v.y; a[m2][2] = v.z; a[m2][3] = v.w;
            }
            uint32_t b[4][2];
            asm volatile("ldmatrix.sync.aligned.m8n8.x4.shared.b16 {%0,%1,%2,%3}, [%4];"
                : "=r"(b[0][0]), "=r"(b[0][1]), "=r"(b[1][0]), "=r"(b[1][1])
                : "r"(bbase + bA1 + s2 * 32));
            asm volatile("ldmatrix.sync.aligned.m8n8.x4.shared.b16 {%0,%1,%2,%3}, [%4];"
                : "=r"(b[2][0]), "=r"(b[2][1]), "=r"(b[3][0]), "=r"(b[3][1])
                : "r"(bbase + bA2 + s2 * 32));
#pragma unroll
            for (int m2 = 0; m2 < 2; m2++)
#pragma unroll
                for (int j = 0; j < 4; j++) {
                    asm volatile(
                        "mma.sync.aligned.m16n8k16.row.col.f32.bf16.bf16.f32 "
                        "{%0,%1,%2,%3}, {%4,%5,%6,%7}, {%8,%9}, {%0,%1,%2,%3};"
                        : "+f"(acc[m2][j][0]), "+f"(acc[m2][j][1]),
                          "+f"(acc[m2][j][2]), "+f"(acc[m2][j][3])
                        : "r"(a[m2][0]), "r"(a[m2][1]), "r"(a[m2][2]), "r"(a[m2][3]),
                          "r"(b[j][0]), "r"(b[j][1]));
                }
        }

        if (q2 == 3) {
            const int nb = tile * 128 + wn * 32;
            float2 cb2[4];
#pragma unroll
            for (int j = 0; j < 4; j++)
                cb2[j] = *(const float2*)(cbn + nb + j * 8 + 2 * tg);
#pragma unroll
            for (int mh = 0; mh < 4; mh++) {
                const int m = mh >> 1, h = mh & 1;
                float d0[8];
#pragma unroll
                for (int j = 0; j < 4; j++) {
                    d0[2 * j]     = acc[m][j][2 * h]     + cb2[j].x;
                    d0[2 * j + 1] = acc[m][j][2 * h + 1] + cb2[j].y;
                }
                float lm = d0[0];
#pragma unroll
                for (int i = 1; i < 8; i++) lm = fminf(lm, d0[i]);
                lm = fminf(lm, __shfl_xor_sync(0xffffffffu, lm, 1));
                lm = fminf(lm, __shfl_xor_sync(0xffffffffu, lm, 2));
                if (lm < minv[mh] + DELTA) {
                    const float thr2 = fminf(minv[mh], lm) + DELTA;
                    const int tl = m * 16 + h * 8 + g;
#pragma unroll
                    for (int j = 0; j < 4; j++)
#pragma unroll
                        for (int p = 0; p < 2; p++) {
                            float d = d0[2 * j + p];
                            if (d < thr2) {
                                int slot = atomicAdd(&snc[wid * 32 + tl], 1);
                                if (slot < CAND_CAP) {
                                    scand[(wid * 32 + tl) * CAND_CAP + slot] =
                                        nb + j * 8 + 2 * tg + p;
                                    scandd[(wid * 32 + tl) * CAND_CAP + slot] = d;
                                }
                            }
                        }
                    minv[mh] = fminf(minv[mh], lm);
                }
            }
        }
    }

    if (tg == 0) {
#pragma unroll
        for (int mh = 0; mh < 4; mh++) {
            const int tl = (mh >> 1) * 16 + (mh & 1) * 8 + g;
            sminv[wid * 32 + tl] = minv[mh];
        }
    }
    __syncthreads();

    // -------- merge + filter --------
    if (tid < 128) {
        const int wmg = tid >> 5, tl = tid & 31;
        const int tok = n_base + tid;
        float gmin = 3.4e38f;
#pragma unroll
        for (int j = 0; j < 4; j++)
            gmin = fminf(gmin, sminv[(wmg * 4 + j) * 32 + tl]);
        const float thr = gmin + DELTA;
        int total = 0;
        bool ovf = false;
        for (int j = 0; j < 4; j++) {
            const int w = wmg * 4 + j;
            int cnum = snc[w * 32 + tl];
            if (cnum > CAND_CAP) { ovf = true; cnum = CAND_CAP; }
            for (int s = 0; s < cnum; s++) {
                if (scandd[(w * 32 + tl) * CAND_CAP + s] <= thr) {
                    g_ck[tok * CK_STRIDE + total] = scand[(w * 32 + tl) * CAND_CAP + s];
                    total++;
                }
            }
        }
        g_nc[tok] = ovf ? 255 : total;
    }
}

// ===================== exact rescoring (fast path nc==1) =====================
__device__ __forceinline__ float vq_exact_dist(const float* __restrict__ cb,
                                               const float zr[8], int k, int lane) {
    const float* cr = cb + (size_t)k * NC + lane;
    float s = 0.f;
#pragma unroll
    for (int u = 0; u < 8; u++) s += zr[u] * cr[u * 32];
#pragma unroll
    for (int off = 16; off; off >>= 1) s += __shfl_xor_sync(0xffffffffu, s, off);
    return g_cbnorm[k] - 2.0f * s;
}

__global__ void vq_rescore_kernel(const float* __restrict__ cb) {
    int n = (blockIdx.x * blockDim.x + threadIdx.x) >> 5;
    int lane = threadIdx.x & 31;
    if (n >= NTOK) return;
    int nc = g_nc[n];

    if (nc == 1) {
        if (lane == 0) g_idx[n] = g_ck[n * CK_STRIDE];
        return;
    }

    const float* zp = g_zt + (size_t)n * NC;
    float zr[8];
#pragma unroll
    for (int u = 0; u < 8; u++) zr[u] = zp[lane + u * 32];

    float bd = 3.4e38f;
    int bk = 0x7fffffff;
    if (nc < 255) {
        for (int i = 0; i < nc; i++) {
            int k = g_ck[n * CK_STRIDE + i];
            float d = vq_exact_dist(cb, zr, k, lane);
            if (d < bd || (d == bd && k < bk)) { bd = d; bk = k; }
        }
    } else {
        for (int k = 0; k < NK; k++) {
            float d = vq_exact_dist(cb, zr, k, lane);
            if (d < bd || (d == bd && k < bk)) { bd = d; bk = k; }
        }
    }
    if (lane == 0) g_idx[n] = bk;
}

// ===================== writeback: 8 channels per thread =====================
__global__ void vq_writeback_kernel(const float* __restrict__ z, const float* __restrict__ cb,
                                    float* __restrict__ out) {
    const int tid = threadIdx.x;
    const int gid = blockIdx.x * 256 + tid;      // over NQ/8
    const int hw  = gid & 1023;
    const int co  = (gid >> 10) & 31;            // 8-channel group
    const int b   = gid >> 15;
    const int n   = (b << 10) | hw;
    const int c   = co * 8;

    const int k = g_idx[n];
    float4 q0 = *(const float4*)(cb + (size_t)k * NC + c);
    float4 q1 = *(const float4*)(cb + (size_t)k * NC + c + 4);

    const size_t zb0 = ((size_t)b * NC + c) * NHW + hw;
    float zv[8];
#pragma unroll
    for (int i = 0; i < 8; i++) zv[i] = z[zb0 + (size_t)i * NHW];

    float qv[8] = {q0.x, q0.y, q0.z, q0.w, q1.x, q1.y, q1.z, q1.w};
#pragma unroll
    for (int i = 0; i < 8; i++)
        out[zb0 + (size_t)i * NHW] = zv[i] + (qv[i] - zv[i]);

    if (co == 0) {
        atomicAdd(&g_counts[k], 1);
        out[NQ + n] = (float)k;
    }

    double s = 0.0;
#pragma unroll
    for (int i = 0; i < 8; i++) {
        float d = zv[i] - qv[i];
        s += (double)d * (double)d;
    }
#pragma unroll
    for (int off = 16; off; off >>= 1) s += __shfl_down_sync(0xffffffffu, s, off);
    __shared__ double ws[8];
    if ((tid & 31) == 0) ws[tid >> 5] = s;
    __syncthreads();
    if (tid == 0) {
        double t = 0.0;
#pragma unroll
        for (int i = 0; i < 8; i++) t += ws[i];
        atomicAdd(&g_loss, t);
    }
}

// ===================== finalize =====================
__global__ void vq_finalize_kernel(float* __restrict__ out) {
    const int tid = threadIdx.x;
    double s = 0.0;
    for (int k = tid; k < NK; k += 256) {
        int c = g_counts[k];
        if (c > 0) {
            double p = (double)c / (double)NTOK;
            s += p * log(p);
        }
    }
#pragma unroll
    for (int off = 16; off; off >>= 1) s += __shfl_down_sync(0xffffffffu, s, off);
    __shared__ double ws[8];
    if ((tid & 31) == 0) ws[tid >> 5] = s;
    __syncthreads();
    if (tid == 0) {
        double t = 0.0;
#pragma unroll
        for (int i = 0; i < 8; i++) t += ws[i];
        float perp = (float)exp(-t);
        float loss = (float)(g_loss / (double)NQ);
        out[NQ + NTOK + 0] = perp;
        out[NQ + NTOK + 1] = loss;
        out[NQ + NTOK + 2] = loss;
    }
}

// ===================== launch =====================
extern "C" void kernel_launch(void* const* d_in, const int* in_sizes, int n_in,
                              void* d_out, int out_size) {
    const float* z  = (const float*)d_in[0];
    const float* cb = (const float*)d_in[1];
    float* out = (float*)d_out;

    static bool attr_set = false;
    if (!attr_set) {
        cudaFuncSetAttribute(vq_argmin_mma_kernel,
                             cudaFuncAttributeMaxDynamicSharedMemorySize, SM_TOTAL);
        attr_set = true;
    }

    vq_prep_kernel<<<2048, 256>>>(z, cb);
    vq_argmin_mma_kernel<<<NTOK / 128, 512, SM_TOTAL>>>();
    vq_rescore_kernel<<<NTOK / 8, 256>>>(cb);
    vq_writeback_kernel<<<NQ / 2048, 256>>>(z, cb, out);
    vq_finalize_kernel<<<1, 256>>>(out);
}

// round 16
// speedup vs baseline: 1.0417x; 1.0095x over previous
#include <cuda_runtime.h>
#include <cuda_bf16.h>
#include <math.h>
#include <stdint.h>

// ===================== problem constants =====================
#define NB   16
#define NC   256
#define NHW  1024
#define NTOK (NB * NHW)        // 16384
#define NK   8192
#define NQ   (NB * NC * NHW)   // 4194304

#define DELTA 0.75f
#define CAND_CAP 16
#define CK_STRIDE 64

// ===================== device scratch =====================
__device__ __align__(16) __nv_bfloat16 g_ebf[NK * NC];            // 4MB, bf16(-2e)
__device__ float  g_cbnorm[NK];
__device__ __align__(16) int g_idx[NTOK];
__device__ int    g_nc[NTOK];
__device__ int    g_ck[NTOK * CK_STRIDE];
__device__ int    g_counts[NK];
__device__ double g_loss;

__device__ __forceinline__ uint32_t smem_u32(const void* p) {
    uint32_t a;
    asm("{ .reg .u64 t; cvta.to.shared.u64 t, %1; cvt.u32.u64 %0, t; }" : "=r"(a) : "l"(p));
    return a;
}

// ===================== prep: cbnorm + bf16(-2e) + init (codebook only) ======
__global__ void vq_prep_cb_kernel(const float* __restrict__ cb) {
    int row  = blockIdx.x * 8 + (threadIdx.x >> 5);
    int lane = threadIdx.x & 31;
    const float* rp = cb + (size_t)row * NC;
    float v[8];
    float s = 0.f;
#pragma unroll
    for (int i = 0; i < 8; i++) {
        v[i] = rp[lane + i * 32];
        s += v[i] * v[i];
    }
#pragma unroll
    for (int off = 16; off; off >>= 1) s += __shfl_down_sync(0xffffffffu, s, off);
    if (lane == 0) g_cbnorm[row] = s;
#pragma unroll
    for (int i = 0; i < 8; i++)
        g_ebf[(size_t)row * NC + lane + i * 32] = __float2bfloat16(-2.0f * v[i]);
    int gid = blockIdx.x * 256 + threadIdx.x;
    if (gid < NK) g_counts[gid] = 0;
    if (gid == 0) g_loss = 0.0;
}

// ===================== main kernel: in-prologue A-frag build + HMMA + filter ==========
#define SM_A      0
#define SM_B      65536
#define SM_BSTG   18432
#define BROW_STRIDE 144
#define SM_CBN    102400
#define SM_SNC    135168
#define SM_SCAND  137216
#define SM_SCANDD 169984
#define SM_SMINV  202752
#define SM_TOTAL  204800

__global__ void __launch_bounds__(512, 1) vq_argmin_mma_kernel(const float* __restrict__ z) {
    extern __shared__ char smem[];
    uint32_t sb = smem_u32(smem);
    const int tid  = threadIdx.x;
    const int wid  = tid >> 5;
    const int lane = tid & 31;
    const int wm   = wid >> 2;       // 0..3
    const int wn   = wid & 3;        // 0..3
    const int g    = lane >> 2;      // 0..7
    const int tg   = lane & 3;       // 0..3
    const int blk  = blockIdx.x;
    const int n_base = blk * 128;
    const int zb   = blk >> 3;           // batch
    const int hw0  = (blk & 7) * 128;    // hw offset

    uint4*  Asm    = (uint4*)(smem + SM_A);
    uint32_t* Aw   = (uint32_t*)(smem + SM_A);
    float*  cbn    = (float*)(smem + SM_CBN);
    int*    snc    = (int*)(smem + SM_SNC);
    int*    scand  = (int*)(smem + SM_SCAND);
    float*  scandd = (float*)(smem + SM_SCANDD);
    float*  sminv  = (float*)(smem + SM_SMINV);

    // ---- build A frags directly from z; stage cbnorm; zero counters ----
    {
        // warp wid handles channel pairs cp = wid*8 .. wid*8+7
#pragma unroll
        for (int i = 0; i < 8; i++) {
            const int cp = wid * 8 + i;
            const int c  = 2 * cp;
            const float* z0 = z + ((size_t)(zb * NC + c)) * NHW + hw0;
            const float* z1 = z0 + NHW;
            const int ks = c >> 4;
            const int kk = c & 15;
            const int ctg = (kk >> 1) & 3;
            const int crh = kk >> 3;
#pragma unroll
            for (int q = 0; q < 4; q++) {
                const int m = lane + q * 32;
                float v0 = z0[m];
                float v1 = z1[m];
                uint32_t lo = (uint32_t)__bfloat16_as_ushort(__float2bfloat16(v0));
                uint32_t hi = (uint32_t)__bfloat16_as_ushort(__float2bfloat16(v1));
                const int mt  = m >> 4;
                const int m15 = m & 15;
                const int gg  = m15 & 7;
                const int rl  = m15 >> 3;
                Aw[(((ks * 8 + mt) * 32) + gg * 4 + ctg) * 4 + rl + 2 * crh] = lo | (hi << 16);
            }
        }
        const float4* cs = (const float4*)g_cbnorm;
        float4* cd = (float4*)cbn;
#pragma unroll
        for (int i = 0; i < 4; i++) cd[tid + i * 512] = cs[tid + i * 512];
        snc[tid] = 0;
    }
    __syncthreads();

    // ---- cp.async B loader ----
    const int brow = tid >> 2;        // 0..127
    const int bq   = tid & 3;         // 32B quarter
    {
        const char* src = (const char*)(g_ebf) + (size_t)brow * 512 + bq * 32;
        uint32_t dst = sb + SM_B + brow * BROW_STRIDE + bq * 32;
        asm volatile("cp.async.cg.shared.global [%0], [%1], 16;" :: "r"(dst), "l"(src));
        asm volatile("cp.async.cg.shared.global [%0], [%1], 16;" :: "r"(dst + 16), "l"(src + 16));
        asm volatile("cp.async.commit_group;" ::: "memory");
    }

    float acc[2][4][4];
    float minv[4];
#pragma unroll
    for (int i = 0; i < 4; i++) minv[i] = 3.4e38f;

    const int rowsel = lane >> 4;
    const int kbsel  = ((lane >> 3) & 1) * 16;
    const uint32_t bA1 = (uint32_t)(((wn * 4 + rowsel) * 8 + (lane & 7)) * BROW_STRIDE + kbsel);
    const uint32_t bA2 = (uint32_t)(((wn * 4 + 2 + rowsel) * 8 + (lane & 7)) * BROW_STRIDE + kbsel);

    for (int T = 0; T < 256; T++) {
        const int tile = T >> 2;
        const int q2   = T & 3;

        asm volatile("cp.async.wait_group 0;" ::: "memory");
        __syncthreads();

        if (T + 1 < 256) {
            const int Tn = T + 1;
            const char* src = (const char*)(g_ebf) +
                (size_t)((Tn >> 2) * 128 + brow) * 512 + (Tn & 3) * 128 + bq * 32;
            uint32_t dst = sb + SM_B + ((Tn & 1) * SM_BSTG) + brow * BROW_STRIDE + bq * 32;
            asm volatile("cp.async.cg.shared.global [%0], [%1], 16;" :: "r"(dst), "l"(src));
            asm volatile("cp.async.cg.shared.global [%0], [%1], 16;" :: "r"(dst + 16), "l"(src + 16));
            asm volatile("cp.async.commit_group;" ::: "memory");
        }

        if (q2 == 0) {
#pragma unroll
            for (int m = 0; m < 2; m++)
#pragma unroll
                for (int j = 0; j < 4; j++)
#pragma unroll
                    for (int r = 0; r < 4; r++) acc[m][j][r] = 0.f;
        }

        const uint32_t bbase = sb + SM_B + (T & 1) * SM_BSTG;
#pragma unroll
        for (int s2 = 0; s2 < 4; s2++) {
            const int ks = q2 * 4 + s2;
            uint32_t a[2][4];
#pragma unroll
            for (int m2 = 0; m2 < 2; m2++) {
                uint4 v = Asm[(ks * 8 + (wm * 2 + m2)) * 32 + lane];
                a[m2][0] = v.x; a[m2][1] = v.y; a[m2][2] = v.z; a[m2][3] = v.w;
            }
            uint32_t b[4][2];
            asm volatile("ldmatrix.sync.aligned.m8n8.x4.shared.b16 {%0,%1,%2,%3}, [%4];"
                : "=r"(b[0][0]), "=r"(b[0][1]), "=r"(b[1][0]), "=r"(b[1][1])
                : "r"(bbase + bA1 + s2 * 32));
            asm volatile("ldmatrix.sync.aligned.m8n8.x4.shared.b16 {%0,%1,%2,%3}, [%4];"
                : "=r"(b[2][0]), "=r"(b[2][1]), "=r"(b[3][0]), "=r"(b[3][1])
                : "r"(bbase + bA2 + s2 * 32));
#pragma unroll
            for (int m2 = 0; m2 < 2; m2++)
#pragma unroll
                for (int j = 0; j < 4; j++) {
                    asm volatile(
                        "mma.sync.aligned.m16n8k16.row.col.f32.bf16.bf16.f32 "
                        "{%0,%1,%2,%3}, {%4,%5,%6,%7}, {%8,%9}, {%0,%1,%2,%3};"
                        : "+f"(acc[m2][j][0]), "+f"(acc[m2][j][1]),
                          "+f"(acc[m2][j][2]), "+f"(acc[m2][j][3])
                        : "r"(a[m2][0]), "r"(a[m2][1]), "r"(a[m2][2]), "r"(a[m2][3]),
                          "r"(b[j][0]), "r"(b[j][1]));
                }
        }

        if (q2 == 3) {
            const int nb = tile * 128 + wn * 32;
            float2 cb2[4];
#pragma unroll
            for (int j = 0; j < 4; j++)
                cb2[j] = *(const float2*)(cbn + nb + j * 8 + 2 * tg);
#pragma unroll
            for (int mh = 0; mh < 4; mh++) {
                const int m = mh >> 1, h = mh & 1;
                float d0[8];
#pragma unroll
                for (int j = 0; j < 4; j++) {
                    d0[2 * j]     = acc[m][j][2 * h]     + cb2[j].x;
                    d0[2 * j + 1] = acc[m][j][2 * h + 1] + cb2[j].y;
                }
                float lm = d0[0];
#pragma unroll
                for (int i = 1; i < 8; i++) lm = fminf(lm, d0[i]);
                lm = fminf(lm, __shfl_xor_sync(0xffffffffu, lm, 1));
                lm = fminf(lm, __shfl_xor_sync(0xffffffffu, lm, 2));
                if (lm < minv[mh] + DELTA) {
                    const float thr2 = fminf(minv[mh], lm) + DELTA;
                    const int tl = m * 16 + h * 8 + g;
#pragma unroll
                    for (int j = 0; j < 4; j++)
#pragma unroll
                        for (int p = 0; p < 2; p++) {
                            float d = d0[2 * j + p];
                            if (d < thr2) {
                                int slot = atomicAdd(&snc[wid * 32 + tl], 1);
                                if (slot < CAND_CAP) {
                                    scand[(wid * 32 + tl) * CAND_CAP + slot] =
                                        nb + j * 8 + 2 * tg + p;
                                    scandd[(wid * 32 + tl) * CAND_CAP + slot] = d;
                                }
                            }
                        }
                    minv[mh] = fminf(minv[mh], lm);
                }
            }
        }
    }

    if (tg == 0) {
#pragma unroll
        for (int mh = 0; mh < 4; mh++) {
            const int tl = (mh >> 1) * 16 + (mh & 1) * 8 + g;
            sminv[wid * 32 + tl] = minv[mh];
        }
    }
    __syncthreads();

    // -------- merge + filter --------
    if (tid < 128) {
        const int wmg = tid >> 5, tl = tid & 31;
        const int tok = n_base + tid;
        float gmin = 3.4e38f;
#pragma unroll
        for (int j = 0; j < 4; j++)
            gmin = fminf(gmin, sminv[(wmg * 4 + j) * 32 + tl]);
        const float thr = gmin + DELTA;
        int total = 0;
        bool ovf = false;
        for (int j = 0; j < 4; j++) {
            const int w = wmg * 4 + j;
            int cnum = snc[w * 32 + tl];
            if (cnum > CAND_CAP) { ovf = true; cnum = CAND_CAP; }
            for (int s = 0; s < cnum; s++) {
                if (scandd[(w * 32 + tl) * CAND_CAP + s] <= thr) {
                    g_ck[tok * CK_STRIDE + total] = scand[(w * 32 + tl) * CAND_CAP + s];
                    total++;
                }
            }
        }
        g_nc[tok] = ovf ? 255 : total;
    }
}

// ===================== exact rescoring (fast path nc==1; strided z) =============
__device__ __forceinline__ float vq_exact_dist(const float* __restrict__ cb,
                                               const float zr[8], int k, int lane) {
    const float* cr = cb + (size_t)k * NC + lane;
    float s = 0.f;
#pragma unroll
    for (int u = 0; u < 8; u++) s += zr[u] * cr[u * 32];
#pragma unroll
    for (int off = 16; off; off >>= 1) s += __shfl_xor_sync(0xffffffffu, s, off);
    return g_cbnorm[k] - 2.0f * s;
}

__global__ void vq_rescore_kernel(const float* __restrict__ z, const float* __restrict__ cb) {
    int n = (blockIdx.x * blockDim.x + threadIdx.x) >> 5;
    int lane = threadIdx.x & 31;
    if (n >= NTOK) return;
    int nc = g_nc[n];

    if (nc == 1) {
        if (lane == 0) g_idx[n] = g_ck[n * CK_STRIDE];
        return;
    }

    int b = n >> 10, hw = n & 1023;
    const float* zp = z + (size_t)b * NC * NHW + hw;
    float zr[8];
#pragma unroll
    for (int u = 0; u < 8; u++) zr[u] = zp[(size_t)(lane + u * 32) * NHW];

    float bd = 3.4e38f;
    int bk = 0x7fffffff;
    if (nc < 255) {
        for (int i = 0; i < nc; i++) {
            int k = g_ck[n * CK_STRIDE + i];
            float d = vq_exact_dist(cb, zr, k, lane);
            if (d < bd || (d == bd && k < bk)) { bd = d; bk = k; }
        }
    } else {
        for (int k = 0; k < NK; k++) {
            float d = vq_exact_dist(cb, zr, k, lane);
            if (d < bd || (d == bd && k < bk)) { bd = d; bk = k; }
        }
    }
    if (lane == 0) g_idx[n] = bk;
}

// ===================== writeback: 8 channels per thread =====================
__global__ void vq_writeback_kernel(const float* __restrict__ z, const float* __restrict__ cb,
                                    float* __restrict__ out) {
    const int tid = threadIdx.x;
    const int gid = blockIdx.x * 256 + tid;      // over NQ/8
    const int hw  = gid & 1023;
    const int co  = (gid >> 10) & 31;            // 8-channel group
    const int b   = gid >> 15;
    const int n   = (b << 10) | hw;
    const int c   = co * 8;

    const int k = g_idx[n];
    float4 q0 = *(const float4*)(cb + (size_t)k * NC + c);
    float4 q1 = *(const float4*)(cb + (size_t)k * NC + c + 4);

    const size_t zb0 = ((size_t)b * NC + c) * NHW + hw;
    float zv[8];
#pragma unroll
    for (int i = 0; i < 8; i++) zv[i] = z[zb0 + (size_t)i * NHW];

    float qv[8] = {q0.x, q0.y, q0.z, q0.w, q1.x, q1.y, q1.z, q1.w};
#pragma unroll
    for (int i = 0; i < 8; i++)
        out[zb0 + (size_t)i * NHW] = zv[i] + (qv[i] - zv[i]);

    if (co == 0) {
        atomicAdd(&g_counts[k], 1);
        out[NQ + n] = (float)k;
    }

    double s = 0.0;
#pragma unroll
    for (int i = 0; i < 8; i++) {
        float d = zv[i] - qv[i];
        s += (double)d * (double)d;
    }
#pragma unroll
    for (int off = 16; off; off >>= 1) s += __shfl_down_sync(0xffffffffu, s, off);
    __shared__ double ws[8];
    if ((tid & 31) == 0) ws[tid >> 5] = s;
    __syncthreads();
    if (tid == 0) {
        double t = 0.0;
#pragma unroll
        for (int i = 0; i < 8; i++) t += ws[i];
        atomicAdd(&g_loss, t);
    }
}

// ===================== finalize =====================
__global__ void vq_finalize_kernel(float* __restrict__ out) {
    const int tid = threadIdx.x;
    double s = 0.0;
    for (int k = tid; k < NK; k += 256) {
        int c = g_counts[k];
        if (c > 0) {
            double p = (double)c / (double)NTOK;
            s += p * log(p);
        }
    }
#pragma unroll
    for (int off = 16; off; off >>= 1) s += __shfl_down_sync(0xffffffffu, s, off);
    __shared__ double ws[8];
    if ((tid & 31) == 0) ws[tid >> 5] = s;
    __syncthreads();
    if (tid == 0) {
        double t = 0.0;
#pragma unroll
        for (int i = 0; i < 8; i++) t += ws[i];
        float perp = (float)exp(-t);
        float loss = (float)(g_loss / (double)NQ);
        out[NQ + NTOK + 0] = perp;
        out[NQ + NTOK + 1] = loss;
        out[NQ + NTOK + 2] = loss;
    }
}

// ===================== launch =====================
extern "C" void kernel_launch(void* const* d_in, const int* in_sizes, int n_in,
                              void* d_out, int out_size) {
    const float* z  = (const float*)d_in[0];
    const float* cb = (const float*)d_in[1];
    float* out = (float*)d_out;

    static bool attr_set = false;
    if (!attr_set) {
        cudaFuncSetAttribute(vq_argmin_mma_kernel,
                             cudaFuncAttributeMaxDynamicSharedMemorySize, SM_TOTAL);
        attr_set = true;
    }

    vq_prep_cb_kernel<<<NK / 8, 256>>>(cb);
    vq_argmin_mma_kernel<<<NTOK / 128, 512, SM_TOTAL>>>(z);
    vq_rescore_kernel<<<NTOK / 8, 256>>>(z, cb);
    vq_writeback_kernel<<<NQ / 2048, 256>>>(z, cb, out);
    vq_finalize_kernel<<<1, 256>>>(out);
}

// round 17
// speedup vs baseline: 1.0419x; 1.0002x over previous
#include <cuda_runtime.h>
#include <cuda_bf16.h>
#include <math.h>
#include <stdint.h>

// ===================== problem constants =====================
#define NB   16
#define NC   256
#define NHW  1024
#define NTOK (NB * NHW)        // 16384
#define NK   8192
#define NQ   (NB * NC * NHW)   // 4194304

#define DELTA 0.75f
#define PACK_MARGIN 0.5f
#define CAND_CAP 16
#define CK_STRIDE 64

// ===================== device scratch =====================
__device__ __align__(16) __nv_bfloat16 g_ebf[NK * NC];            // 4MB, bf16(-2e)
__device__ float  g_cbnorm[NK];
__device__ __align__(16) int g_idx[NTOK];
__device__ int    g_nc[NTOK];
__device__ int    g_ck[NTOK * CK_STRIDE];
__device__ int    g_counts[NK];
__device__ double g_loss;

__device__ __forceinline__ uint32_t smem_u32(const void* p) {
    uint32_t a;
    asm("{ .reg .u64 t; cvta.to.shared.u64 t, %1; cvt.u32.u64 %0, t; }" : "=r"(a) : "l"(p));
    return a;
}

// ===================== prep: cbnorm + bf16(-2e) + init (codebook only) ======
__global__ void vq_prep_cb_kernel(const float* __restrict__ cb) {
    int row  = blockIdx.x * 8 + (threadIdx.x >> 5);
    int lane = threadIdx.x & 31;
    const float* rp = cb + (size_t)row * NC;
    float v[8];
    float s = 0.f;
#pragma unroll
    for (int i = 0; i < 8; i++) {
        v[i] = rp[lane + i * 32];
        s += v[i] * v[i];
    }
#pragma unroll
    for (int off = 16; off; off >>= 1) s += __shfl_down_sync(0xffffffffu, s, off);
    if (lane == 0) g_cbnorm[row] = s;
#pragma unroll
    for (int i = 0; i < 8; i++)
        g_ebf[(size_t)row * NC + lane + i * 32] = __float2bfloat16(-2.0f * v[i]);
    int gid = blockIdx.x * 256 + threadIdx.x;
    if (gid < NK) g_counts[gid] = 0;
    if (gid == 0) g_loss = 0.0;
}

// ===================== main kernel: in-prologue A build + HMMA + packed filter ========
#define SM_A      0
#define SM_B      65536
#define SM_BSTG   18432
#define BROW_STRIDE 144
#define SM_CBN    102400
#define SM_SNC    135168
#define SM_SCANDP 137216
#define SM_SMINV  169984
#define SM_TOTAL  172032

__global__ void __launch_bounds__(512, 1) vq_argmin_mma_kernel(const float* __restrict__ z) {
    extern __shared__ char smem[];
    uint32_t sb = smem_u32(smem);
    const int tid  = threadIdx.x;
    const int wid  = tid >> 5;
    const int lane = tid & 31;
    const int wm   = wid >> 2;       // 0..3
    const int wn   = wid & 3;        // 0..3
    const int g    = lane >> 2;      // 0..7
    const int tg   = lane & 3;       // 0..3
    const int blk  = blockIdx.x;
    const int n_base = blk * 128;
    const int zb   = blk >> 3;           // batch
    const int hw0  = (blk & 7) * 128;    // hw offset

    uint4*  Asm    = (uint4*)(smem + SM_A);
    uint32_t* Aw   = (uint32_t*)(smem + SM_A);
    float*  cbn    = (float*)(smem + SM_CBN);
    int*    snc    = (int*)(smem + SM_SNC);
    uint32_t* scandp = (uint32_t*)(smem + SM_SCANDP);   // [16][32][16] packed (bf16 d | k)
    float*  sminv  = (float*)(smem + SM_SMINV);

    // ---- build A frags directly from z; stage cbnorm; zero counters ----
    {
#pragma unroll
        for (int i = 0; i < 8; i++) {
            const int cp = wid * 8 + i;
            const int c  = 2 * cp;
            const float* z0 = z + ((size_t)(zb * NC + c)) * NHW + hw0;
            const float* z1 = z0 + NHW;
            const int ks = c >> 4;
            const int kk = c & 15;
            const int ctg = (kk >> 1) & 3;
            const int crh = kk >> 3;
#pragma unroll
            for (int q = 0; q < 4; q++) {
                const int m = lane + q * 32;
                float v0 = z0[m];
                float v1 = z1[m];
                uint32_t lo = (uint32_t)__bfloat16_as_ushort(__float2bfloat16(v0));
                uint32_t hi = (uint32_t)__bfloat16_as_ushort(__float2bfloat16(v1));
                const int mt  = m >> 4;
                const int m15 = m & 15;
                const int gg  = m15 & 7;
                const int rl  = m15 >> 3;
                Aw[(((ks * 8 + mt) * 32) + gg * 4 + ctg) * 4 + rl + 2 * crh] = lo | (hi << 16);
            }
        }
        const float4* cs = (const float4*)g_cbnorm;
        float4* cd = (float4*)cbn;
#pragma unroll
        for (int i = 0; i < 4; i++) cd[tid + i * 512] = cs[tid + i * 512];
        snc[tid] = 0;
    }
    __syncthreads();

    // ---- cp.async B loader ----
    const int brow = tid >> 2;        // 0..127
    const int bq   = tid & 3;         // 32B quarter
    {
        const char* src = (const char*)(g_ebf) + (size_t)brow * 512 + bq * 32;
        uint32_t dst = sb + SM_B + brow * BROW_STRIDE + bq * 32;
        asm volatile("cp.async.cg.shared.global [%0], [%1], 16;" :: "r"(dst), "l"(src));
        asm volatile("cp.async.cg.shared.global [%0], [%1], 16;" :: "r"(dst + 16), "l"(src + 16));
        asm volatile("cp.async.commit_group;" ::: "memory");
    }

    float acc[2][4][4];
    float minv[4];
#pragma unroll
    for (int i = 0; i < 4; i++) minv[i] = 3.4e38f;

    const int rowsel = lane >> 4;
    const int kbsel  = ((lane >> 3) & 1) * 16;
    const uint32_t bA1 = (uint32_t)(((wn * 4 + rowsel) * 8 + (lane & 7)) * BROW_STRIDE + kbsel);
    const uint32_t bA2 = (uint32_t)(((wn * 4 + 2 + rowsel) * 8 + (lane & 7)) * BROW_STRIDE + kbsel);

    for (int T = 0; T < 256; T++) {
        const int tile = T >> 2;
        const int q2   = T & 3;

        asm volatile("cp.async.wait_group 0;" ::: "memory");
        __syncthreads();

        if (T + 1 < 256) {
            const int Tn = T + 1;
            const char* src = (const char*)(g_ebf) +
                (size_t)((Tn >> 2) * 128 + brow) * 512 + (Tn & 3) * 128 + bq * 32;
            uint32_t dst = sb + SM_B + ((Tn & 1) * SM_BSTG) + brow * BROW_STRIDE + bq * 32;
            asm volatile("cp.async.cg.shared.global [%0], [%1], 16;" :: "r"(dst), "l"(src));
            asm volatile("cp.async.cg.shared.global [%0], [%1], 16;" :: "r"(dst + 16), "l"(src + 16));
            asm volatile("cp.async.commit_group;" ::: "memory");
        }

        if (q2 == 0) {
#pragma unroll
            for (int m = 0; m < 2; m++)
#pragma unroll
                for (int j = 0; j < 4; j++)
#pragma unroll
                    for (int r = 0; r < 4; r++) acc[m][j][r] = 0.f;
        }

        const uint32_t bbase = sb + SM_B + (T & 1) * SM_BSTG;
#pragma unroll
        for (int s2 = 0; s2 < 4; s2++) {
            const int ks = q2 * 4 + s2;
            uint32_t a[2][4];
#pragma unroll
            for (int m2 = 0; m2 < 2; m2++) {
                uint4 v = Asm[(ks * 8 + (wm * 2 + m2)) * 32 + lane];
                a[m2][0] = v.x; a[m2][1] = v.y; a[m2][2] = v.z; a[m2][3] = v.w;
            }
            uint32_t b[4][2];
            asm volatile("ldmatrix.sync.aligned.m8n8.x4.shared.b16 {%0,%1,%2,%3}, [%4];"
                : "=r"(b[0][0]), "=r"(b[0][1]), "=r"(b[1][0]), "=r"(b[1][1])
                : "r"(bbase + bA1 + s2 * 32));
            asm volatile("ldmatrix.sync.aligned.m8n8.x4.shared.b16 {%0,%1,%2,%3}, [%4];"
                : "=r"(b[2][0]), "=r"(b[2][1]), "=r"(b[3][0]), "=r"(b[3][1])
                : "r"(bbase + bA2 + s2 * 32));
#pragma unroll
            for (int m2 = 0; m2 < 2; m2++)
#pragma unroll
                for (int j = 0; j < 4; j++) {
                    asm volatile(
                        "mma.sync.aligned.m16n8k16.row.col.f32.bf16.bf16.f32 "
                        "{%0,%1,%2,%3}, {%4,%5,%6,%7}, {%8,%9}, {%0,%1,%2,%3};"
                        : "+f"(acc[m2][j][0]), "+f"(acc[m2][j][1]),
                          "+f"(acc[m2][j][2]), "+f"(acc[m2][j][3])
                        : "r"(a[m2][0]), "r"(a[m2][1]), "r"(a[m2][2]), "r"(a[m2][3]),
                          "r"(b[j][0]), "r"(b[j][1]));
                }
        }

        if (q2 == 3) {
            const int nb = tile * 128 + wn * 32;
            float2 cb2[4];
#pragma unroll
            for (int j = 0; j < 4; j++)
                cb2[j] = *(const float2*)(cbn + nb + j * 8 + 2 * tg);
#pragma unroll
            for (int mh = 0; mh < 4; mh++) {
                const int m = mh >> 1, h = mh & 1;
                float d0[8];
#pragma unroll
                for (int j = 0; j < 4; j++) {
                    d0[2 * j]     = acc[m][j][2 * h]     + cb2[j].x;
                    d0[2 * j + 1] = acc[m][j][2 * h + 1] + cb2[j].y;
                }
                float lm = d0[0];
#pragma unroll
                for (int i = 1; i < 8; i++) lm = fminf(lm, d0[i]);
                lm = fminf(lm, __shfl_xor_sync(0xffffffffu, lm, 1));
                lm = fminf(lm, __shfl_xor_sync(0xffffffffu, lm, 2));
                if (lm < minv[mh] + DELTA) {
                    const float thr2 = fminf(minv[mh], lm) + DELTA;
                    const int tl = m * 16 + h * 8 + g;
#pragma unroll
                    for (int j = 0; j < 4; j++)
#pragma unroll
                        for (int p = 0; p < 2; p++) {
                            float d = d0[2 * j + p];
                            if (d < thr2) {
                                int slot = atomicAdd(&snc[wid * 32 + tl], 1);
                                if (slot < CAND_CAP) {
                                    uint32_t db =
                                        (uint32_t)__bfloat16_as_ushort(__float2bfloat16(d));
                                    scandp[(wid * 32 + tl) * CAND_CAP + slot] =
                                        (db << 16) | (uint32_t)(nb + j * 8 + 2 * tg + p);
                                }
                            }
                        }
                    minv[mh] = fminf(minv[mh], lm);
                }
            }
        }
    }

    if (tg == 0) {
#pragma unroll
        for (int mh = 0; mh < 4; mh++) {
            const int tl = (mh >> 1) * 16 + (mh & 1) * 8 + g;
            sminv[wid * 32 + tl] = minv[mh];
        }
    }
    __syncthreads();

    // -------- merge + filter (bf16 distance, widened margin) --------
    if (tid < 128) {
        const int wmg = tid >> 5, tl = tid & 31;
        const int tok = n_base + tid;
        float gmin = 3.4e38f;
#pragma unroll
        for (int j = 0; j < 4; j++)
            gmin = fminf(gmin, sminv[(wmg * 4 + j) * 32 + tl]);
        const float thr = gmin + DELTA + PACK_MARGIN;
        int total = 0;
        bool ovf = false;
        for (int j = 0; j < 4; j++) {
            const int w = wmg * 4 + j;
            int cnum = snc[w * 32 + tl];
            if (cnum > CAND_CAP) { ovf = true; cnum = CAND_CAP; }
            for (int s = 0; s < cnum; s++) {
                uint32_t pk = scandp[(w * 32 + tl) * CAND_CAP + s];
                float df = __bfloat162float(__ushort_as_bfloat16((unsigned short)(pk >> 16)));
                if (df <= thr) {
                    g_ck[tok * CK_STRIDE + total] = (int)(pk & 0xFFFFu);
                    total++;
                }
            }
        }
        g_nc[tok] = ovf ? 255 : total;
    }
}

// ===================== exact rescoring (fast path nc==1; strided z) =============
__device__ __forceinline__ float vq_exact_dist(const float* __restrict__ cb,
                                               const float zr[8], int k, int lane) {
    const float* cr = cb + (size_t)k * NC + lane;
    float s = 0.f;
#pragma unroll
    for (int u = 0; u < 8; u++) s += zr[u] * cr[u * 32];
#pragma unroll
    for (int off = 16; off; off >>= 1) s += __shfl_xor_sync(0xffffffffu, s, off);
    return g_cbnorm[k] - 2.0f * s;
}

__global__ void vq_rescore_kernel(const float* __restrict__ z, const float* __restrict__ cb) {
    int n = (blockIdx.x * blockDim.x + threadIdx.x) >> 5;
    int lane = threadIdx.x & 31;
    if (n >= NTOK) return;
    int nc = g_nc[n];

    if (nc == 1) {
        if (lane == 0) g_idx[n] = g_ck[n * CK_STRIDE];
        return;
    }

    int b = n >> 10, hw = n & 1023;
    const float* zp = z + (size_t)b * NC * NHW + hw;
    float zr[8];
#pragma unroll
    for (int u = 0; u < 8; u++) zr[u] = zp[(size_t)(lane + u * 32) * NHW];

    float bd = 3.4e38f;
    int bk = 0x7fffffff;
    if (nc < 255) {
        for (int i = 0; i < nc; i++) {
            int k = g_ck[n * CK_STRIDE + i];
            float d = vq_exact_dist(cb, zr, k, lane);
            if (d < bd || (d == bd && k < bk)) { bd = d; bk = k; }
        }
    } else {
        for (int k = 0; k < NK; k++) {
            float d = vq_exact_dist(cb, zr, k, lane);
            if (d < bd || (d == bd && k < bk)) { bd = d; bk = k; }
        }
    }
    if (lane == 0) g_idx[n] = bk;
}

// ===================== writeback: 16 channels per thread =====================
__global__ void vq_writeback_kernel(const float* __restrict__ z, const float* __restrict__ cb,
                                    float* __restrict__ out) {
    const int tid = threadIdx.x;
    const int gid = blockIdx.x * 256 + tid;      // over NQ/16
    const int hw  = gid & 1023;
    const int co  = (gid >> 10) & 15;            // 16-channel group
    const int b   = gid >> 14;
    const int n   = (b << 10) | hw;
    const int c   = co * 16;

    const int k = g_idx[n];
    float qv[16];
#pragma unroll
    for (int u = 0; u < 4; u++) {
        float4 q = *(const float4*)(cb + (size_t)k * NC + c + 4 * u);
        qv[4 * u] = q.x; qv[4 * u + 1] = q.y; qv[4 * u + 2] = q.z; qv[4 * u + 3] = q.w;
    }

    const size_t zb0 = ((size_t)b * NC + c) * NHW + hw;
    float zv[16];
#pragma unroll
    for (int i = 0; i < 16; i++) zv[i] = z[zb0 + (size_t)i * NHW];

#pragma unroll
    for (int i = 0; i < 16; i++)
        out[zb0 + (size_t)i * NHW] = zv[i] + (qv[i] - zv[i]);

    if (co == 0) {
        atomicAdd(&g_counts[k], 1);
        out[NQ + n] = (float)k;
    }

    double s = 0.0;
#pragma unroll
    for (int i = 0; i < 16; i++) {
        float d = zv[i] - qv[i];
        s += (double)d * (double)d;
    }
#pragma unroll
    for (int off = 16; off; off >>= 1) s += __shfl_down_sync(0xffffffffu, s, off);
    __shared__ double ws[8];
    if ((tid & 31) == 0) ws[tid >> 5] = s;
    __syncthreads();
    if (tid == 0) {
        double t = 0.0;
#pragma unroll
        for (int i = 0; i < 8; i++) t += ws[i];
        atomicAdd(&g_loss, t);
    }
}

// ===================== finalize =====================
__global__ void vq_finalize_kernel(float* __restrict__ out) {
    const int tid = threadIdx.x;
    double s = 0.0;
    for (int k = tid; k < NK; k += 256) {
        int c = g_counts[k];
        if (c > 0) {
            double p = (double)c / (double)NTOK;
            s += p * log(p);
        }
    }
#pragma unroll
    for (int off = 16; off; off >>= 1) s += __shfl_down_sync(0xffffffffu, s, off);
    __shared__ double ws[8];
    if ((tid & 31) == 0) ws[tid >> 5] = s;
    __syncthreads();
    if (tid == 0) {
        double t = 0.0;
#pragma unroll
        for (int i = 0; i < 8; i++) t += ws[i];
        float perp = (float)exp(-t);
        float loss = (float)(g_loss / (double)NQ);
        out[NQ + NTOK + 0] = perp;
        out[NQ + NTOK + 1] = loss;
        out[NQ + NTOK + 2] = loss;
    }
}

// ===================== launch =====================
extern "C" void kernel_launch(void* const* d_in, const int* in_sizes, int n_in,
                              void* d_out, int out_size) {
    const float* z  = (const float*)d_in[0];
    const float* cb = (const float*)d_in[1];
    float* out = (float*)d_out;

    static bool attr_set = false;
    if (!attr_set) {
        cudaFuncSetAttribute(vq_argmin_mma_kernel,
                             cudaFuncAttributeMaxDynamicSharedMemorySize, SM_TOTAL);
        attr_set = true;
    }

    vq_prep_cb_kernel<<<NK / 8, 256>>>(cb);
    vq_argmin_mma_kernel<<<NTOK / 128, 512, SM_TOTAL>>>(z);
    vq_rescore_kernel<<<NTOK / 8, 256>>>(z, cb);
    vq_writeback_kernel<<<NQ / 4096, 256>>>(z, cb, out);
    vq_finalize_kernel<<<1, 256>>>(out);
}